// round 15
// baseline (speedup 1.0000x reference)
#include <cuda_runtime.h>
#include <cuda_bf16.h>
#include <cuda_fp16.h>
#include <cstdint>

// ---------------- problem constants ----------------
static constexpr int Bb  = 16;
static constexpr int Mm  = 1024;
static constexpr int Nn  = 4096;
static constexpr int CIN = 67;
static constexpr int HID = 128;
static constexpr int KS  = 384;          // split-bf16 concat K: [hi|lo|hi] x [hi|hi|lo]
static constexpr int NTILE = Nn / 128;   // 32 n-tiles per row
static constexpr float ESCALE  = 16384.0f;          // 2^14 exponent shift for fp16 e'
static constexpr float IESCALE = 1.0f / 16384.0f;

// ---------------- scratch (device globals; no cudaMalloc allowed) ----------------
__device__ __align__(128) __nv_bfloat16 g_A[(size_t)Bb * Mm * KS];   // 12.6 MB
__device__ __align__(128) __nv_bfloat16 g_Bm[(size_t)Bb * Nn * KS]; // 50 MB
__device__ __align__(128) __half g_T[(size_t)Bb * Mm * Nn];          // 134 MB: e'*2^14 then t (in place)
__device__ float g_partial[Mm / 16][Bb * Nn];                        // colsum partials (16MB)
__device__ float g_rcolsum[Bb * Nn];                                 // reciprocal col L1 sums
__device__ float g_L[(size_t)Bb * Mm * NTILE];                       // per-(row,tile) local max (2MB)
__device__ float g_S[(size_t)Bb * Mm * NTILE];                       // per-(row,tile) local expsum (2MB)
__device__ float g_scale[(size_t)Bb * Mm * NTILE];                   // exp(L-M)/Z (2MB)

__device__ __forceinline__ uint32_t smem_to_u32(const void* p) {
    uint32_t a;
    asm("{ .reg .u64 t; cvta.to.shared.u64 t, %1; cvt.u32.u64 %0, t; }" : "=r"(a) : "l"(p));
    return a;
}

// ================= K1: q/k projection + BN + bf16 split =================
__global__ void __launch_bounds__(128) qk_kernel(
    const float* __restrict__ cent, const float* __restrict__ feat,
    const float* __restrict__ Wq, const float* __restrict__ Wk,
    const float* __restrict__ gq, const float* __restrict__ bq,
    const float* __restrict__ mq, const float* __restrict__ vq,
    const float* __restrict__ gk, const float* __restrict__ bk,
    const float* __restrict__ mk, const float* __restrict__ vk)
{
    __shared__ float sW[HID * CIN];
    __shared__ float sin[CIN];
    const int ROWS = 64;
    long row0 = (long)blockIdx.x * ROWS;
    bool isQ = row0 < (long)Bb * Mm;
    const float* W = isQ ? Wq : Wk;
    for (int i = threadIdx.x; i < HID * CIN; i += blockDim.x) sW[i] = W[i];

    int h = threadIdx.x;
    float g_ = isQ ? gq[h] : gk[h];
    float b_ = isQ ? bq[h] : bk[h];
    float m_ = isQ ? mq[h] : mk[h];
    float v_ = isQ ? vq[h] : vk[h];
    float scale = g_ / sqrtf(v_ + 1e-5f);
    float shift = b_ - m_ * scale;

    const float* X = isQ ? cent : feat;
    long rbase = isQ ? row0 : row0 - (long)Bb * Mm;
    __nv_bfloat16* dst = isQ ? g_A : g_Bm;
    __syncthreads();

    for (int r = 0; r < ROWS; r++) {
        long row = rbase + r;
        if (threadIdx.x < CIN) sin[threadIdx.x] = X[row * CIN + threadIdx.x];
        __syncthreads();
        float a0 = 0.0f, a1 = 0.0f;
        #pragma unroll 1
        for (int c = 0; c < CIN - 1; c += 2) {
            a0 = fmaf(sin[c],     sW[h * CIN + c],     a0);
            a1 = fmaf(sin[c + 1], sW[h * CIN + c + 1], a1);
        }
        a0 = fmaf(sin[CIN - 1], sW[h * CIN + CIN - 1], a0);
        float out = (a0 + a1) * scale + shift;
        __nv_bfloat16 hi = __float2bfloat16(out);
        __nv_bfloat16 lo = __float2bfloat16(out - __bfloat162float(hi));
        __nv_bfloat16* d = dst + row * (long)KS;
        if (isQ) { d[h] = hi; d[HID + h] = lo; d[2 * HID + h] = hi; }
        else     { d[h] = hi; d[HID + h] = hi; d[2 * HID + h] = lo; }
        __syncthreads();
    }
}

// ================= K2: GEMM + fused split-N softmax phase 1 =================
static constexpr int CH    = 64;
static constexpr int NCH   = KS / CH;             // 6
static constexpr int PITCH = CH * 2 + 16;         // 144 B/row
static constexpr int STG_T = 128 * PITCH;         // 18432
static constexpr int STG   = 2 * STG_T;           // 36864
static constexpr int GEMM_SMEM = 3 * STG;         // 110592

__device__ __forceinline__ void ldsm_x4(uint32_t& r0, uint32_t& r1, uint32_t& r2, uint32_t& r3,
                                        uint32_t addr) {
    asm volatile("ldmatrix.sync.aligned.m8n8.x4.shared.b16 {%0,%1,%2,%3}, [%4];"
                 : "=r"(r0), "=r"(r1), "=r"(r2), "=r"(r3) : "r"(addr));
}
__device__ __forceinline__ void mma_16816(float* c, const uint32_t* a, const uint32_t* b) {
    asm volatile("mma.sync.aligned.m16n8k16.row.col.f32.bf16.bf16.f32 "
                 "{%0,%1,%2,%3}, {%4,%5,%6,%7}, {%8,%9}, {%0,%1,%2,%3};"
                 : "+f"(c[0]), "+f"(c[1]), "+f"(c[2]), "+f"(c[3])
                 : "r"(a[0]), "r"(a[1]), "r"(a[2]), "r"(a[3]), "r"(b[0]), "r"(b[1]));
}
__device__ __forceinline__ void cp16(uint32_t saddr, const void* g) {
    asm volatile("cp.async.cg.shared.global [%0], [%1], 16;" :: "r"(saddr), "l"(g));
}

__device__ __forceinline__ void load_stage(const char* gA, const char* gB,
                                           uint32_t stage_base, int tid)
{
    #pragma unroll
    for (int j = 0; j < 4; j++) {
        int i = tid + j * 256;
        int row = i >> 3, seg = i & 7;
        uint32_t so = (uint32_t)(row * PITCH + seg * 16);
        size_t   go = (size_t)row * (KS * 2) + seg * 16;
        cp16(stage_base + so,         gA + go);
        cp16(stage_base + STG_T + so, gB + go);
    }
    asm volatile("cp.async.commit_group;" ::: "memory");
}

__global__ void __launch_bounds__(256, 2) gemm_kernel(const float* __restrict__ mask)
{
    extern __shared__ char smem[];
    uint32_t sbase = smem_to_u32(smem);
    int tid = threadIdx.x, wid = tid >> 5, lane = tid & 31;
    int nb = blockIdx.x, mb = blockIdx.y, b = blockIdx.z;

    const char* gA = reinterpret_cast<const char*>(g_A)  + (size_t)(b * Mm + mb * 128) * KS * 2;
    const char* gB = reinterpret_cast<const char*>(g_Bm) + (size_t)(b * Nn + nb * 128) * KS * 2;

    load_stage(gA,          gB,          sbase,       tid);
    load_stage(gA + CH * 2, gB + CH * 2, sbase + STG, tid);

    int wm = wid >> 2;
    int wn = wid & 3;
    uint32_t aRowOff = (uint32_t)((wm * 64 + (lane & 15)) * PITCH + ((lane >> 4) * 8) * 2);
    uint32_t bRowOff = (uint32_t)(STG_T + (wn * 32 + (lane & 7) + ((lane >> 4) & 1) * 8) * PITCH
                                  + (((lane >> 3) & 1) * 8) * 2);

    float c[4][4][4];
    #pragma unroll
    for (int i = 0; i < 4; i++)
        #pragma unroll
        for (int j = 0; j < 4; j++)
            #pragma unroll
            for (int r = 0; r < 4; r++) c[i][j][r] = 0.0f;

    int st = 0;
    #pragma unroll 1
    for (int ch = 0; ch < NCH; ch++) {
        if (ch < NCH - 2) asm volatile("cp.async.wait_group 1;" ::: "memory");
        else              asm volatile("cp.async.wait_group 0;" ::: "memory");
        __syncthreads();

        if (ch + 2 < NCH) {
            int nst = st + 2; if (nst >= 3) nst -= 3;
            load_stage(gA + (size_t)(ch + 2) * CH * 2, gB + (size_t)(ch + 2) * CH * 2,
                       sbase + nst * STG, tid);
        }

        uint32_t aB = sbase + st * STG + aRowOff;
        uint32_t bB = sbase + st * STG + bRowOff;

        #pragma unroll
        for (int kk = 0; kk < CH / 16; kk++) {
            uint32_t kOff = (uint32_t)(kk * 32);
            uint32_t a[4][4];
            #pragma unroll
            for (int mi = 0; mi < 4; mi++)
                ldsm_x4(a[mi][0], a[mi][1], a[mi][2], a[mi][3],
                        aB + (uint32_t)(mi * 16 * PITCH) + kOff);
            uint32_t bf[4][2];
            #pragma unroll
            for (int p = 0; p < 2; p++) {
                uint32_t r0, r1, r2, r3;
                ldsm_x4(r0, r1, r2, r3, bB + (uint32_t)(p * 16 * PITCH) + kOff);
                bf[2 * p][0] = r0;     bf[2 * p][1] = r1;
                bf[2 * p + 1][0] = r2; bf[2 * p + 1][1] = r3;
            }
            #pragma unroll
            for (int mi = 0; mi < 4; mi++)
                #pragma unroll
                for (int nj = 0; nj < 4; nj++)
                    mma_16816(c[mi][nj], a[mi], bf[nj]);
        }

        if (++st >= 3) st -= 3;
    }

    // ---------- fused epilogue: mask, per-tile row max, exp, e'*2^14 fp16, (L,S) ----------
    __syncthreads();                                   // mainloop smem dead
    float* redm = reinterpret_cast<float*>(smem);      // [128][4]
    float* rowL = redm + 128 * 4;                      // [128]
    float* reds = rowL + 128;                          // [128][4]

    int g = lane >> 2, tg = lane & 3;
    long rowBase = (long)(b * Mm + mb * 128 + wm * 64);
    int colBase = nb * 128 + wn * 32 + 2 * tg;

    // P0+P1: apply mask, per-row local max over this warp's 8 cols, 4-lane reduce
    #pragma unroll
    for (int mi = 0; mi < 4; mi++) {
        float v0 = -3.0e38f, v1 = -3.0e38f;
        #pragma unroll
        for (int nj = 0; nj < 4; nj++) {
            const float* q0 = mask + (rowBase + mi * 16 + g) * Nn + colBase + nj * 8;
            const float* q1 = mask + (rowBase + mi * 16 + g + 8) * Nn + colBase + nj * 8;
            float2 m0 = *reinterpret_cast<const float2*>(q0);
            float2 m1 = *reinterpret_cast<const float2*>(q1);
            if (m0.x < 1e-9f) c[mi][nj][0] = -1e9f;
            if (m0.y < 1e-9f) c[mi][nj][1] = -1e9f;
            if (m1.x < 1e-9f) c[mi][nj][2] = -1e9f;
            if (m1.y < 1e-9f) c[mi][nj][3] = -1e9f;
            v0 = fmaxf(v0, fmaxf(c[mi][nj][0], c[mi][nj][1]));
            v1 = fmaxf(v1, fmaxf(c[mi][nj][2], c[mi][nj][3]));
        }
        #pragma unroll
        for (int o = 1; o < 4; o <<= 1) {
            v0 = fmaxf(v0, __shfl_xor_sync(0xffffffffu, v0, o));
            v1 = fmaxf(v1, __shfl_xor_sync(0xffffffffu, v1, o));
        }
        if (tg == 0) {
            redm[(wm * 64 + mi * 16 + g) * 4 + wn]     = v0;
            redm[(wm * 64 + mi * 16 + g + 8) * 4 + wn] = v1;
        }
    }
    __syncthreads();
    if (tid < 128)
        rowL[tid] = fmaxf(fmaxf(redm[tid * 4], redm[tid * 4 + 1]),
                          fmaxf(redm[tid * 4 + 2], redm[tid * 4 + 3]));
    __syncthreads();

    // P2: e' = exp(x - L), store e'*2^14 fp16 (avoids subnormal blowup), per-row sums
    #pragma unroll
    for (int mi = 0; mi < 4; mi++) {
        float L0 = rowL[wm * 64 + mi * 16 + g];
        float L1 = rowL[wm * 64 + mi * 16 + g + 8];
        float s0 = 0.0f, s1 = 0.0f;
        #pragma unroll
        for (int nj = 0; nj < 4; nj++) {
            float e0 = __expf(c[mi][nj][0] - L0);
            float e1 = __expf(c[mi][nj][1] - L0);
            float e2 = __expf(c[mi][nj][2] - L1);
            float e3 = __expf(c[mi][nj][3] - L1);
            s0 += e0 + e1; s1 += e2 + e3;
            *reinterpret_cast<__half2*>(g_T + (rowBase + mi * 16 + g) * (size_t)Nn
                                        + colBase + nj * 8)
                = __floats2half2_rn(e0 * ESCALE, e1 * ESCALE);
            *reinterpret_cast<__half2*>(g_T + (rowBase + mi * 16 + g + 8) * (size_t)Nn
                                        + colBase + nj * 8)
                = __floats2half2_rn(e2 * ESCALE, e3 * ESCALE);
        }
        #pragma unroll
        for (int o = 1; o < 4; o <<= 1) {
            s0 += __shfl_xor_sync(0xffffffffu, s0, o);
            s1 += __shfl_xor_sync(0xffffffffu, s1, o);
        }
        if (tg == 0) {
            reds[(wm * 64 + mi * 16 + g) * 4 + wn]     = s0;
            reds[(wm * 64 + mi * 16 + g + 8) * 4 + wn] = s1;
        }
    }
    __syncthreads();
    if (tid < 128) {
        float S = reds[tid * 4] + reds[tid * 4 + 1] + reds[tid * 4 + 2] + reds[tid * 4 + 3];
        size_t idx = ((size_t)b * Mm + mb * 128 + tid) * NTILE + nb;
        g_L[idx] = rowL[tid];
        g_S[idx] = S;
    }
}

// ================= K2b: combine per-row tile stats -> scales =================
__global__ void __launch_bounds__(512) combine_kernel()
{
    int row = blockIdx.x * 16 + (threadIdx.x >> 5);   // one warp per row
    int lane = threadIdx.x & 31;
    size_t idx = (size_t)row * NTILE + lane;
    float L = g_L[idx];
    float S = g_S[idx];
    float M = L;
    #pragma unroll
    for (int o = 16; o; o >>= 1) M = fmaxf(M, __shfl_xor_sync(0xffffffffu, M, o));
    float el = __expf(L - M);
    float Z = S * el;
    #pragma unroll
    for (int o = 16; o; o >>= 1) Z += __shfl_xor_sync(0xffffffffu, Z, o);
    g_scale[idx] = el / Z * IESCALE;     // fold the 2^-14 unscale into a
}

// ================= K3: streaming transform: t = sqrt((m+eps)(e''*a+eps)), col partials ====
__global__ void __launch_bounds__(512) transform_kernel(const float* __restrict__ mask)
{
    int mblk = blockIdx.x;          // 0..63
    int b = blockIdx.y;             // 0..15
    int tid = threadIdx.x;

    float ca[8];
    #pragma unroll
    for (int j = 0; j < 8; j++) ca[j] = 0.0f;

    #pragma unroll 1
    for (int r = 0; r < 16; r++) {
        long row = (long)b * Mm + mblk * 16 + r;
        const float4* mr = reinterpret_cast<const float4*>(mask + row * Nn);
        uint2* tp = reinterpret_cast<uint2*>(g_T + row * Nn);
        const float* ap = g_scale + (size_t)row * NTILE;

        #pragma unroll
        for (int j = 0; j < 2; j++) {
            int vi = tid + j * 512;
            float a = ap[(4 * vi) >> 7];
            float4 m = mr[vi];
            uint2 ev = tp[vi];
            const __half* hp = reinterpret_cast<const __half*>(&ev);
            __half h4[4];
            float mm[4] = {m.x, m.y, m.z, m.w};
            #pragma unroll
            for (int k = 0; k < 4; k++) {
                float p = __half2float(hp[k]) * a;
                float t = sqrtf((mm[k] + 1e-9f) * (p + 1e-9f)) - 1e-9f;
                h4[k] = __float2half_rn(t);
                ca[j * 4 + k] += __half2float(h4[k]);
            }
            tp[vi] = *reinterpret_cast<uint2*>(h4);
        }
    }

    float4* part = reinterpret_cast<float4*>(g_partial[mblk] + b * Nn);
    #pragma unroll
    for (int j = 0; j < 2; j++) {
        float4 o;
        o.x = ca[j * 4 + 0]; o.y = ca[j * 4 + 1];
        o.z = ca[j * 4 + 2]; o.w = ca[j * 4 + 3];
        part[tid + j * 512] = o;
    }
}

// ================= K3b: finalize column sums =================
__global__ void __launch_bounds__(256) colsum_fin_kernel()
{
    int i = blockIdx.x * 256 + threadIdx.x;
    float s = 0.0f;
    #pragma unroll
    for (int ms = 0; ms < Mm / 16; ms++) s += g_partial[ms][i];
    g_rcolsum[i] = 1.0f / fmaxf(s, 1e-12f);
}

// ================= block sum reduce (512 threads) =================
__device__ __forceinline__ float block_sum(float v, float* red)
{
    int tid = threadIdx.x, lid = tid & 31, wid = tid >> 5;
    #pragma unroll
    for (int o = 16; o; o >>= 1) v += __shfl_xor_sync(0xffffffffu, v, o);
    if (lid == 0) red[wid] = v;
    __syncthreads();
    if (wid == 0) {
        float w = (lid < 16) ? red[lid] : 0.0f;
        #pragma unroll
        for (int o = 8; o; o >>= 1) w += __shfl_xor_sync(0xffffffffu, w, o);
        if (lid == 0) red[0] = w;
    }
    __syncthreads();
    float r = red[0];
    __syncthreads();
    return r;
}

// ================= K4: column norm + row norm (half t in, fp32 out) =================
__global__ void __launch_bounds__(512) norm_kernel(float* __restrict__ out)
{
    __shared__ float red[16];
    long row = blockIdx.x;
    int b = (int)(row >> 10);
    const uint2* tr = reinterpret_cast<const uint2*>(g_T + row * Nn);
    const float4* rc = reinterpret_cast<const float4*>(g_rcolsum + b * Nn);
    float4* ow = reinterpret_cast<float4*>(out + row * Nn);
    int tid = threadIdx.x;

    float u[2][4];
    float s = 0.0f;
    #pragma unroll
    for (int j = 0; j < 2; j++) {
        uint2 tv = tr[tid + j * 512];
        const __half* hp = reinterpret_cast<const __half*>(&tv);
        float4 r = rc[tid + j * 512];
        u[j][0] = __half2float(hp[0]) * r.x;
        u[j][1] = __half2float(hp[1]) * r.y;
        u[j][2] = __half2float(hp[2]) * r.z;
        u[j][3] = __half2float(hp[3]) * r.w;
        s += u[j][0] + u[j][1] + u[j][2] + u[j][3];
    }
    s = block_sum(s, red);
    float inv = 1.0f / fmaxf(s, 1e-12f);
    #pragma unroll
    for (int j = 0; j < 2; j++) {
        float4 o;
        o.x = u[j][0] * inv; o.y = u[j][1] * inv;
        o.z = u[j][2] * inv; o.w = u[j][3] * inv;
        ow[tid + j * 512] = o;
    }
}

// ================= launch =================
extern "C" void kernel_launch(void* const* d_in, const int* in_sizes, int n_in,
                              void* d_out, int out_size)
{
    const float* cent = (const float*)d_in[0];
    const float* feat = (const float*)d_in[1];
    const float* mask = (const float*)d_in[2];
    const float* Wq = (const float*)d_in[3];
    const float* Wk = (const float*)d_in[4];
    const float* gq = (const float*)d_in[5];
    const float* bq = (const float*)d_in[6];
    const float* mq = (const float*)d_in[7];
    const float* vq = (const float*)d_in[8];
    const float* gk = (const float*)d_in[9];
    const float* bk = (const float*)d_in[10];
    const float* mk = (const float*)d_in[11];
    const float* vk = (const float*)d_in[12];
    float* out = (float*)d_out;

    qk_kernel<<<(Bb * Mm + Bb * Nn) / 64, 128>>>(cent, feat, Wq, Wk,
                                                 gq, bq, mq, vq, gk, bk, mk, vk);

    cudaFuncSetAttribute(gemm_kernel, cudaFuncAttributeMaxDynamicSharedMemorySize, GEMM_SMEM);
    gemm_kernel<<<dim3(Nn / 128, Mm / 128, Bb), 256, GEMM_SMEM>>>(mask);

    combine_kernel<<<(Bb * Mm) / 16, 512>>>();

    transform_kernel<<<dim3(Mm / 16, Bb), 512>>>(mask);

    colsum_fin_kernel<<<(Bb * Nn) / 256, 256>>>();

    norm_kernel<<<Bb * Mm, 512>>>(out);
}

// round 16
// speedup vs baseline: 1.0027x; 1.0027x over previous
#include <cuda_runtime.h>
#include <cuda_bf16.h>
#include <cuda_fp16.h>
#include <cstdint>

// ---------------- problem constants ----------------
static constexpr int Bb  = 16;
static constexpr int Mm  = 1024;
static constexpr int Nn  = 4096;
static constexpr int CIN = 67;
static constexpr int HID = 128;
static constexpr int KS  = 384;          // split-bf16 concat K: [hi|lo|hi] x [hi|hi|lo]
static constexpr int NTILE = Nn / 128;   // 32 n-tiles per row
static constexpr float ESCALE  = 16384.0f;          // 2^14 exponent shift for fp16 e'
static constexpr float IESCALE = 1.0f / 16384.0f;

// ---------------- scratch (device globals; no cudaMalloc allowed) ----------------
__device__ __align__(128) __nv_bfloat16 g_A[(size_t)Bb * Mm * KS];   // 12.6 MB
__device__ __align__(128) __nv_bfloat16 g_Bm[(size_t)Bb * Nn * KS]; // 50 MB
__device__ __align__(128) __half g_T[(size_t)Bb * Mm * Nn];          // 134 MB: e'*2^14 then t (in place)
__device__ float g_partial[Mm / 16][Bb * Nn];                        // colsum partials (16MB)
__device__ float g_rcolsum[Bb * Nn];                                 // reciprocal col L1 sums
__device__ float g_L[(size_t)Bb * Mm * NTILE];                       // per-(row,tile) local max (2MB)
__device__ float g_S[(size_t)Bb * Mm * NTILE];                       // per-(row,tile) local expsum (2MB)
__device__ float g_scale[(size_t)Bb * Mm * NTILE];                   // exp(L-M)/Z * 2^-14 (2MB)

__device__ __forceinline__ uint32_t smem_to_u32(const void* p) {
    uint32_t a;
    asm("{ .reg .u64 t; cvta.to.shared.u64 t, %1; cvt.u32.u64 %0, t; }" : "=r"(a) : "l"(p));
    return a;
}

// ================= K1: q/k projection + BN + bf16 split =================
__global__ void __launch_bounds__(128) qk_kernel(
    const float* __restrict__ cent, const float* __restrict__ feat,
    const float* __restrict__ Wq, const float* __restrict__ Wk,
    const float* __restrict__ gq, const float* __restrict__ bq,
    const float* __restrict__ mq, const float* __restrict__ vq,
    const float* __restrict__ gk, const float* __restrict__ bk,
    const float* __restrict__ mk, const float* __restrict__ vk)
{
    __shared__ float sW[HID * CIN];
    __shared__ float sin[CIN];
    const int ROWS = 64;
    long row0 = (long)blockIdx.x * ROWS;
    bool isQ = row0 < (long)Bb * Mm;
    const float* W = isQ ? Wq : Wk;
    for (int i = threadIdx.x; i < HID * CIN; i += blockDim.x) sW[i] = W[i];

    int h = threadIdx.x;
    float g_ = isQ ? gq[h] : gk[h];
    float b_ = isQ ? bq[h] : bk[h];
    float m_ = isQ ? mq[h] : mk[h];
    float v_ = isQ ? vq[h] : vk[h];
    float scale = g_ / sqrtf(v_ + 1e-5f);
    float shift = b_ - m_ * scale;

    const float* X = isQ ? cent : feat;
    long rbase = isQ ? row0 : row0 - (long)Bb * Mm;
    __nv_bfloat16* dst = isQ ? g_A : g_Bm;
    __syncthreads();

    for (int r = 0; r < ROWS; r++) {
        long row = rbase + r;
        if (threadIdx.x < CIN) sin[threadIdx.x] = X[row * CIN + threadIdx.x];
        __syncthreads();
        float a0 = 0.0f, a1 = 0.0f;
        #pragma unroll 1
        for (int c = 0; c < CIN - 1; c += 2) {
            a0 = fmaf(sin[c],     sW[h * CIN + c],     a0);
            a1 = fmaf(sin[c + 1], sW[h * CIN + c + 1], a1);
        }
        a0 = fmaf(sin[CIN - 1], sW[h * CIN + CIN - 1], a0);
        float out = (a0 + a1) * scale + shift;
        __nv_bfloat16 hi = __float2bfloat16(out);
        __nv_bfloat16 lo = __float2bfloat16(out - __bfloat162float(hi));
        __nv_bfloat16* d = dst + row * (long)KS;
        if (isQ) { d[h] = hi; d[HID + h] = lo; d[2 * HID + h] = hi; }
        else     { d[h] = hi; d[HID + h] = hi; d[2 * HID + h] = lo; }
        __syncthreads();
    }
}

// ================= K2: GEMM + fused split-N softmax phase 1 =================
static constexpr int CH    = 64;
static constexpr int NCH   = KS / CH;             // 6
static constexpr int PITCH = CH * 2 + 16;         // 144 B/row
static constexpr int STG_T = 128 * PITCH;         // 18432
static constexpr int STG   = 2 * STG_T;           // 36864
static constexpr int GEMM_SMEM = 3 * STG;         // 110592

__device__ __forceinline__ void ldsm_x4(uint32_t& r0, uint32_t& r1, uint32_t& r2, uint32_t& r3,
                                        uint32_t addr) {
    asm volatile("ldmatrix.sync.aligned.m8n8.x4.shared.b16 {%0,%1,%2,%3}, [%4];"
                 : "=r"(r0), "=r"(r1), "=r"(r2), "=r"(r3) : "r"(addr));
}
__device__ __forceinline__ void mma_16816(float* c, const uint32_t* a, const uint32_t* b) {
    asm volatile("mma.sync.aligned.m16n8k16.row.col.f32.bf16.bf16.f32 "
                 "{%0,%1,%2,%3}, {%4,%5,%6,%7}, {%8,%9}, {%0,%1,%2,%3};"
                 : "+f"(c[0]), "+f"(c[1]), "+f"(c[2]), "+f"(c[3])
                 : "r"(a[0]), "r"(a[1]), "r"(a[2]), "r"(a[3]), "r"(b[0]), "r"(b[1]));
}
__device__ __forceinline__ void cp16(uint32_t saddr, const void* g) {
    asm volatile("cp.async.cg.shared.global [%0], [%1], 16;" :: "r"(saddr), "l"(g));
}

__device__ __forceinline__ void load_stage(const char* gA, const char* gB,
                                           uint32_t stage_base, int tid)
{
    #pragma unroll
    for (int j = 0; j < 4; j++) {
        int i = tid + j * 256;
        int row = i >> 3, seg = i & 7;
        uint32_t so = (uint32_t)(row * PITCH + seg * 16);
        size_t   go = (size_t)row * (KS * 2) + seg * 16;
        cp16(stage_base + so,         gA + go);
        cp16(stage_base + STG_T + so, gB + go);
    }
    asm volatile("cp.async.commit_group;" ::: "memory");
}

__global__ void __launch_bounds__(256, 2) gemm_kernel(const float* __restrict__ mask)
{
    extern __shared__ char smem[];
    uint32_t sbase = smem_to_u32(smem);
    int tid = threadIdx.x, wid = tid >> 5, lane = tid & 31;
    int nb = blockIdx.x, mb = blockIdx.y, b = blockIdx.z;

    const char* gA = reinterpret_cast<const char*>(g_A)  + (size_t)(b * Mm + mb * 128) * KS * 2;
    const char* gB = reinterpret_cast<const char*>(g_Bm) + (size_t)(b * Nn + nb * 128) * KS * 2;

    load_stage(gA,          gB,          sbase,       tid);
    load_stage(gA + CH * 2, gB + CH * 2, sbase + STG, tid);

    int wm = wid >> 2;
    int wn = wid & 3;
    uint32_t aRowOff = (uint32_t)((wm * 64 + (lane & 15)) * PITCH + ((lane >> 4) * 8) * 2);
    uint32_t bRowOff = (uint32_t)(STG_T + (wn * 32 + (lane & 7) + ((lane >> 4) & 1) * 8) * PITCH
                                  + (((lane >> 3) & 1) * 8) * 2);

    float c[4][4][4];
    #pragma unroll
    for (int i = 0; i < 4; i++)
        #pragma unroll
        for (int j = 0; j < 4; j++)
            #pragma unroll
            for (int r = 0; r < 4; r++) c[i][j][r] = 0.0f;

    int st = 0;
    #pragma unroll 1
    for (int ch = 0; ch < NCH; ch++) {
        if (ch < NCH - 2) asm volatile("cp.async.wait_group 1;" ::: "memory");
        else              asm volatile("cp.async.wait_group 0;" ::: "memory");
        __syncthreads();

        if (ch + 2 < NCH) {
            int nst = st + 2; if (nst >= 3) nst -= 3;
            load_stage(gA + (size_t)(ch + 2) * CH * 2, gB + (size_t)(ch + 2) * CH * 2,
                       sbase + nst * STG, tid);
        }

        uint32_t aB = sbase + st * STG + aRowOff;
        uint32_t bB = sbase + st * STG + bRowOff;

        #pragma unroll
        for (int kk = 0; kk < CH / 16; kk++) {
            uint32_t kOff = (uint32_t)(kk * 32);
            uint32_t a[4][4];
            #pragma unroll
            for (int mi = 0; mi < 4; mi++)
                ldsm_x4(a[mi][0], a[mi][1], a[mi][2], a[mi][3],
                        aB + (uint32_t)(mi * 16 * PITCH) + kOff);
            uint32_t bf[4][2];
            #pragma unroll
            for (int p = 0; p < 2; p++) {
                uint32_t r0, r1, r2, r3;
                ldsm_x4(r0, r1, r2, r3, bB + (uint32_t)(p * 16 * PITCH) + kOff);
                bf[2 * p][0] = r0;     bf[2 * p][1] = r1;
                bf[2 * p + 1][0] = r2; bf[2 * p + 1][1] = r3;
            }
            #pragma unroll
            for (int mi = 0; mi < 4; mi++)
                #pragma unroll
                for (int nj = 0; nj < 4; nj++)
                    mma_16816(c[mi][nj], a[mi], bf[nj]);
        }

        if (++st >= 3) st -= 3;
    }

    // ---------- fused epilogue: coalesced mask->smem, max, exp, e'*2^14 fp16, (L,S) ------
    __syncthreads();                                   // mainloop smem dead
    float* smem_m = reinterpret_cast<float*>(smem);    // [128][132] mask tile (67.6KB)
    float* redm = smem_m + 128 * 132;                  // [128][4]
    float* rowL = redm + 128 * 4;                      // [128]
    float* reds = rowL + 128;                          // [128][4]

    long rowTile = (long)(b * Mm + mb * 128);
    int colTile = nb * 128;

    // coalesced mask tile load (float4): 4096 float4, 16 per thread
    #pragma unroll
    for (int it = 0; it < 16; it++) {
        int idx = tid + it * 256;
        int row = idx >> 5, c4 = idx & 31;
        float4 v = *reinterpret_cast<const float4*>(
            mask + (rowTile + row) * Nn + colTile + c4 * 4);
        *reinterpret_cast<float4*>(smem_m + row * 132 + c4 * 4) = v;
    }
    __syncthreads();

    int g = lane >> 2, tg = lane & 3;
    long rowBase = rowTile + wm * 64;
    int lcolBase = wn * 32 + 2 * tg;

    // P1: apply mask (from smem), per-row local max, 4-lane reduce
    #pragma unroll
    for (int mi = 0; mi < 4; mi++) {
        int lr0 = wm * 64 + mi * 16 + g;
        float v0 = -3.0e38f, v1 = -3.0e38f;
        #pragma unroll
        for (int nj = 0; nj < 4; nj++) {
            float2 m0 = *reinterpret_cast<float2*>(smem_m + lr0 * 132 + lcolBase + nj * 8);
            float2 m1 = *reinterpret_cast<float2*>(smem_m + (lr0 + 8) * 132 + lcolBase + nj * 8);
            if (m0.x < 1e-9f) c[mi][nj][0] = -1e9f;
            if (m0.y < 1e-9f) c[mi][nj][1] = -1e9f;
            if (m1.x < 1e-9f) c[mi][nj][2] = -1e9f;
            if (m1.y < 1e-9f) c[mi][nj][3] = -1e9f;
            v0 = fmaxf(v0, fmaxf(c[mi][nj][0], c[mi][nj][1]));
            v1 = fmaxf(v1, fmaxf(c[mi][nj][2], c[mi][nj][3]));
        }
        #pragma unroll
        for (int o = 1; o < 4; o <<= 1) {
            v0 = fmaxf(v0, __shfl_xor_sync(0xffffffffu, v0, o));
            v1 = fmaxf(v1, __shfl_xor_sync(0xffffffffu, v1, o));
        }
        if (tg == 0) {
            redm[(lr0) * 4 + wn]     = v0;
            redm[(lr0 + 8) * 4 + wn] = v1;
        }
    }
    __syncthreads();
    if (tid < 128)
        rowL[tid] = fmaxf(fmaxf(redm[tid * 4], redm[tid * 4 + 1]),
                          fmaxf(redm[tid * 4 + 2], redm[tid * 4 + 3]));
    __syncthreads();

    // P2: e' = exp(x - L), store e'*2^14 fp16, per-row sums
    #pragma unroll
    for (int mi = 0; mi < 4; mi++) {
        float L0 = rowL[wm * 64 + mi * 16 + g];
        float L1 = rowL[wm * 64 + mi * 16 + g + 8];
        float s0 = 0.0f, s1 = 0.0f;
        #pragma unroll
        for (int nj = 0; nj < 4; nj++) {
            float e0 = __expf(c[mi][nj][0] - L0);
            float e1 = __expf(c[mi][nj][1] - L0);
            float e2 = __expf(c[mi][nj][2] - L1);
            float e3 = __expf(c[mi][nj][3] - L1);
            s0 += e0 + e1; s1 += e2 + e3;
            *reinterpret_cast<__half2*>(g_T + (rowBase + mi * 16 + g) * (size_t)Nn
                                        + colTile + lcolBase + nj * 8)
                = __floats2half2_rn(e0 * ESCALE, e1 * ESCALE);
            *reinterpret_cast<__half2*>(g_T + (rowBase + mi * 16 + g + 8) * (size_t)Nn
                                        + colTile + lcolBase + nj * 8)
                = __floats2half2_rn(e2 * ESCALE, e3 * ESCALE);
        }
        #pragma unroll
        for (int o = 1; o < 4; o <<= 1) {
            s0 += __shfl_xor_sync(0xffffffffu, s0, o);
            s1 += __shfl_xor_sync(0xffffffffu, s1, o);
        }
        if (tg == 0) {
            reds[(wm * 64 + mi * 16 + g) * 4 + wn]     = s0;
            reds[(wm * 64 + mi * 16 + g + 8) * 4 + wn] = s1;
        }
    }
    __syncthreads();
    if (tid < 128) {
        float S = reds[tid * 4] + reds[tid * 4 + 1] + reds[tid * 4 + 2] + reds[tid * 4 + 3];
        size_t idx = ((size_t)b * Mm + mb * 128 + tid) * NTILE + nb;
        g_L[idx] = rowL[tid];
        g_S[idx] = S;
    }
}

// ================= K2b: combine per-row tile stats -> scales =================
__global__ void __launch_bounds__(512) combine_kernel()
{
    int row = blockIdx.x * 16 + (threadIdx.x >> 5);   // one warp per row
    int lane = threadIdx.x & 31;
    size_t idx = (size_t)row * NTILE + lane;
    float L = g_L[idx];
    float S = g_S[idx];
    float M = L;
    #pragma unroll
    for (int o = 16; o; o >>= 1) M = fmaxf(M, __shfl_xor_sync(0xffffffffu, M, o));
    float el = __expf(L - M);
    float Z = S * el;
    #pragma unroll
    for (int o = 16; o; o >>= 1) Z += __shfl_xor_sync(0xffffffffu, Z, o);
    g_scale[idx] = el / Z * IESCALE;     // fold the 2^-14 unscale into a
}

// ================= K3: streaming transform: t = sqrt((m+eps)(e''*a+eps)), col partials ====
__global__ void __launch_bounds__(512) transform_kernel(const float* __restrict__ mask)
{
    int mblk = blockIdx.x;          // 0..63
    int b = blockIdx.y;             // 0..15
    int tid = threadIdx.x;

    float ca[8];
    #pragma unroll
    for (int j = 0; j < 8; j++) ca[j] = 0.0f;

    #pragma unroll 1
    for (int r = 0; r < 16; r++) {
        long row = (long)b * Mm + mblk * 16 + r;
        const float4* mr = reinterpret_cast<const float4*>(mask + row * Nn);
        uint2* tp = reinterpret_cast<uint2*>(g_T + row * Nn);
        const float* ap = g_scale + (size_t)row * NTILE;

        #pragma unroll
        for (int j = 0; j < 2; j++) {
            int vi = tid + j * 512;
            float a = ap[(4 * vi) >> 7];
            float4 m = mr[vi];
            uint2 ev = tp[vi];
            const __half* hp = reinterpret_cast<const __half*>(&ev);
            __half h4[4];
            float mm[4] = {m.x, m.y, m.z, m.w};
            #pragma unroll
            for (int k = 0; k < 4; k++) {
                float p = __half2float(hp[k]) * a;
                float t = sqrtf((mm[k] + 1e-9f) * (p + 1e-9f)) - 1e-9f;
                h4[k] = __float2half_rn(t);
                ca[j * 4 + k] += __half2float(h4[k]);
            }
            tp[vi] = *reinterpret_cast<uint2*>(h4);
        }
    }

    float4* part = reinterpret_cast<float4*>(g_partial[mblk] + b * Nn);
    #pragma unroll
    for (int j = 0; j < 2; j++) {
        float4 o;
        o.x = ca[j * 4 + 0]; o.y = ca[j * 4 + 1];
        o.z = ca[j * 4 + 2]; o.w = ca[j * 4 + 3];
        part[tid + j * 512] = o;
    }
}

// ================= K3b: finalize column sums =================
__global__ void __launch_bounds__(256) colsum_fin_kernel()
{
    int i = blockIdx.x * 256 + threadIdx.x;
    float s = 0.0f;
    #pragma unroll
    for (int ms = 0; ms < Mm / 16; ms++) s += g_partial[ms][i];
    g_rcolsum[i] = 1.0f / fmaxf(s, 1e-12f);
}

// ================= block sum reduce (512 threads) =================
__device__ __forceinline__ float block_sum(float v, float* red)
{
    int tid = threadIdx.x, lid = tid & 31, wid = tid >> 5;
    #pragma unroll
    for (int o = 16; o; o >>= 1) v += __shfl_xor_sync(0xffffffffu, v, o);
    if (lid == 0) red[wid] = v;
    __syncthreads();
    if (wid == 0) {
        float w = (lid < 16) ? red[lid] : 0.0f;
        #pragma unroll
        for (int o = 8; o; o >>= 1) w += __shfl_xor_sync(0xffffffffu, w, o);
        if (lid == 0) red[0] = w;
    }
    __syncthreads();
    float r = red[0];
    __syncthreads();
    return r;
}

// ================= K4: column norm + row norm (half t in, fp32 out) =================
__global__ void __launch_bounds__(512) norm_kernel(float* __restrict__ out)
{
    __shared__ float red[16];
    long row = blockIdx.x;
    int b = (int)(row >> 10);
    const uint2* tr = reinterpret_cast<const uint2*>(g_T + row * Nn);
    const float4* rc = reinterpret_cast<const float4*>(g_rcolsum + b * Nn);
    float4* ow = reinterpret_cast<float4*>(out + row * Nn);
    int tid = threadIdx.x;

    float u[2][4];
    float s = 0.0f;
    #pragma unroll
    for (int j = 0; j < 2; j++) {
        uint2 tv = tr[tid + j * 512];
        const __half* hp = reinterpret_cast<const __half*>(&tv);
        float4 r = rc[tid + j * 512];
        u[j][0] = __half2float(hp[0]) * r.x;
        u[j][1] = __half2float(hp[1]) * r.y;
        u[j][2] = __half2float(hp[2]) * r.z;
        u[j][3] = __half2float(hp[3]) * r.w;
        s += u[j][0] + u[j][1] + u[j][2] + u[j][3];
    }
    s = block_sum(s, red);
    float inv = 1.0f / fmaxf(s, 1e-12f);
    #pragma unroll
    for (int j = 0; j < 2; j++) {
        float4 o;
        o.x = u[j][0] * inv; o.y = u[j][1] * inv;
        o.z = u[j][2] * inv; o.w = u[j][3] * inv;
        ow[tid + j * 512] = o;
    }
}

// ================= launch =================
extern "C" void kernel_launch(void* const* d_in, const int* in_sizes, int n_in,
                              void* d_out, int out_size)
{
    const float* cent = (const float*)d_in[0];
    const float* feat = (const float*)d_in[1];
    const float* mask = (const float*)d_in[2];
    const float* Wq = (const float*)d_in[3];
    const float* Wk = (const float*)d_in[4];
    const float* gq = (const float*)d_in[5];
    const float* bq = (const float*)d_in[6];
    const float* mq = (const float*)d_in[7];
    const float* vq = (const float*)d_in[8];
    const float* gk = (const float*)d_in[9];
    const float* bk = (const float*)d_in[10];
    const float* mk = (const float*)d_in[11];
    const float* vk = (const float*)d_in[12];
    float* out = (float*)d_out;

    qk_kernel<<<(Bb * Mm + Bb * Nn) / 64, 128>>>(cent, feat, Wq, Wk,
                                                 gq, bq, mq, vq, gk, bk, mk, vk);

    cudaFuncSetAttribute(gemm_kernel, cudaFuncAttributeMaxDynamicSharedMemorySize, GEMM_SMEM);
    gemm_kernel<<<dim3(Nn / 128, Mm / 128, Bb), 256, GEMM_SMEM>>>(mask);

    combine_kernel<<<(Bb * Mm) / 16, 512>>>();

    transform_kernel<<<dim3(Mm / 16, Bb), 512>>>(mask);

    colsum_fin_kernel<<<(Bb * Nn) / 256, 256>>>();

    norm_kernel<<<Bb * Mm, 512>>>(out);
}

// round 17
// speedup vs baseline: 1.1051x; 1.1021x over previous
#include <cuda_runtime.h>
#include <cuda_bf16.h>
#include <cuda_fp16.h>
#include <cstdint>

// ---------------- problem constants ----------------
static constexpr int Bb  = 16;
static constexpr int Mm  = 1024;
static constexpr int Nn  = 4096;
static constexpr int CIN = 67;
static constexpr int HID = 128;
static constexpr int KS  = 384;          // split-bf16 concat K: [hi|lo|hi] x [hi|hi|lo]

// ---------------- scratch (device globals; no cudaMalloc allowed) ----------------
__device__ __align__(128) __nv_bfloat16 g_A[(size_t)Bb * Mm * KS];   // 12.6 MB
__device__ __align__(128) __nv_bfloat16 g_Bm[(size_t)Bb * Nn * KS]; // 50 MB
__device__ __align__(128) __half g_T[(size_t)Bb * Mm * Nn];          // 134 MB (t, fp16)
__device__ float g_partial[Mm / 16][Bb * Nn];                        // colsum partials (16MB)
__device__ float g_rcolsum[Bb * Nn];                                 // reciprocal col L1 sums

__device__ __forceinline__ uint32_t smem_to_u32(const void* p) {
    uint32_t a;
    asm("{ .reg .u64 t; cvta.to.shared.u64 t, %1; cvt.u32.u64 %0, t; }" : "=r"(a) : "l"(p));
    return a;
}

// ================= K1: q/k projection + BN + bf16 split =================
__global__ void __launch_bounds__(128) qk_kernel(
    const float* __restrict__ cent, const float* __restrict__ feat,
    const float* __restrict__ Wq, const float* __restrict__ Wk,
    const float* __restrict__ gq, const float* __restrict__ bq,
    const float* __restrict__ mq, const float* __restrict__ vq,
    const float* __restrict__ gk, const float* __restrict__ bk,
    const float* __restrict__ mk, const float* __restrict__ vk)
{
    __shared__ float sW[HID * CIN];
    __shared__ float sin[CIN];
    const int ROWS = 64;
    long row0 = (long)blockIdx.x * ROWS;
    bool isQ = row0 < (long)Bb * Mm;
    const float* W = isQ ? Wq : Wk;
    for (int i = threadIdx.x; i < HID * CIN; i += blockDim.x) sW[i] = W[i];

    int h = threadIdx.x;
    float g_ = isQ ? gq[h] : gk[h];
    float b_ = isQ ? bq[h] : bk[h];
    float m_ = isQ ? mq[h] : mk[h];
    float v_ = isQ ? vq[h] : vk[h];
    float scale = g_ / sqrtf(v_ + 1e-5f);
    float shift = b_ - m_ * scale;

    const float* X = isQ ? cent : feat;
    long rbase = isQ ? row0 : row0 - (long)Bb * Mm;
    __nv_bfloat16* dst = isQ ? g_A : g_Bm;
    __syncthreads();

    for (int r = 0; r < ROWS; r++) {
        long row = rbase + r;
        if (threadIdx.x < CIN) sin[threadIdx.x] = X[row * CIN + threadIdx.x];
        __syncthreads();
        float a0 = 0.0f, a1 = 0.0f;
        #pragma unroll 1
        for (int c = 0; c < CIN - 1; c += 2) {
            a0 = fmaf(sin[c],     sW[h * CIN + c],     a0);
            a1 = fmaf(sin[c + 1], sW[h * CIN + c + 1], a1);
        }
        a0 = fmaf(sin[CIN - 1], sW[h * CIN + CIN - 1], a0);
        float out = (a0 + a1) * scale + shift;
        __nv_bfloat16 hi = __float2bfloat16(out);
        __nv_bfloat16 lo = __float2bfloat16(out - __bfloat162float(hi));
        __nv_bfloat16* d = dst + row * (long)KS;
        if (isQ) { d[h] = hi; d[HID + h] = lo; d[2 * HID + h] = hi; }
        else     { d[h] = hi; d[HID + h] = hi; d[2 * HID + h] = lo; }
        __syncthreads();
    }
}

// ================= K2: 3-stage pipelined mma.sync bf16 GEMM =================
static constexpr int CH    = 64;
static constexpr int NCH   = KS / CH;             // 6
static constexpr int PITCH = CH * 2 + 16;         // 144 B/row
static constexpr int STG_T = 128 * PITCH;         // 18432
static constexpr int STG   = 2 * STG_T;           // 36864
static constexpr int GEMM_SMEM = 3 * STG;         // 110592

__device__ __forceinline__ void ldsm_x4(uint32_t& r0, uint32_t& r1, uint32_t& r2, uint32_t& r3,
                                        uint32_t addr) {
    asm volatile("ldmatrix.sync.aligned.m8n8.x4.shared.b16 {%0,%1,%2,%3}, [%4];"
                 : "=r"(r0), "=r"(r1), "=r"(r2), "=r"(r3) : "r"(addr));
}
__device__ __forceinline__ void mma_16816(float* c, const uint32_t* a, const uint32_t* b) {
    asm volatile("mma.sync.aligned.m16n8k16.row.col.f32.bf16.bf16.f32 "
                 "{%0,%1,%2,%3}, {%4,%5,%6,%7}, {%8,%9}, {%0,%1,%2,%3};"
                 : "+f"(c[0]), "+f"(c[1]), "+f"(c[2]), "+f"(c[3])
                 : "r"(a[0]), "r"(a[1]), "r"(a[2]), "r"(a[3]), "r"(b[0]), "r"(b[1]));
}
__device__ __forceinline__ void cp16(uint32_t saddr, const void* g) {
    asm volatile("cp.async.cg.shared.global [%0], [%1], 16;" :: "r"(saddr), "l"(g));
}

__device__ __forceinline__ void load_stage(const char* gA, const char* gB,
                                           uint32_t stage_base, int tid)
{
    #pragma unroll
    for (int j = 0; j < 4; j++) {
        int i = tid + j * 256;
        int row = i >> 3, seg = i & 7;
        uint32_t so = (uint32_t)(row * PITCH + seg * 16);
        size_t   go = (size_t)row * (KS * 2) + seg * 16;
        cp16(stage_base + so,         gA + go);
        cp16(stage_base + STG_T + so, gB + go);
    }
    asm volatile("cp.async.commit_group;" ::: "memory");
}

__global__ void __launch_bounds__(256, 2) gemm_kernel(float* __restrict__ out)
{
    extern __shared__ char smem[];
    uint32_t sbase = smem_to_u32(smem);
    int tid = threadIdx.x, wid = tid >> 5, lane = tid & 31;
    int nb = blockIdx.x, mb = blockIdx.y, b = blockIdx.z;

    const char* gA = reinterpret_cast<const char*>(g_A)  + (size_t)(b * Mm + mb * 128) * KS * 2;
    const char* gB = reinterpret_cast<const char*>(g_Bm) + (size_t)(b * Nn + nb * 128) * KS * 2;

    load_stage(gA,          gB,          sbase,       tid);
    load_stage(gA + CH * 2, gB + CH * 2, sbase + STG, tid);

    int wm = wid >> 2;
    int wn = wid & 3;
    uint32_t aRowOff = (uint32_t)((wm * 64 + (lane & 15)) * PITCH + ((lane >> 4) * 8) * 2);
    uint32_t bRowOff = (uint32_t)(STG_T + (wn * 32 + (lane & 7) + ((lane >> 4) & 1) * 8) * PITCH
                                  + (((lane >> 3) & 1) * 8) * 2);

    float c[4][4][4];
    #pragma unroll
    for (int i = 0; i < 4; i++)
        #pragma unroll
        for (int j = 0; j < 4; j++)
            #pragma unroll
            for (int r = 0; r < 4; r++) c[i][j][r] = 0.0f;

    int st = 0;
    #pragma unroll 1
    for (int ch = 0; ch < NCH; ch++) {
        if (ch < NCH - 2) asm volatile("cp.async.wait_group 1;" ::: "memory");
        else              asm volatile("cp.async.wait_group 0;" ::: "memory");
        __syncthreads();

        if (ch + 2 < NCH) {
            int nst = st + 2; if (nst >= 3) nst -= 3;
            load_stage(gA + (size_t)(ch + 2) * CH * 2, gB + (size_t)(ch + 2) * CH * 2,
                       sbase + nst * STG, tid);
        }

        uint32_t aB = sbase + st * STG + aRowOff;
        uint32_t bB = sbase + st * STG + bRowOff;

        #pragma unroll
        for (int kk = 0; kk < CH / 16; kk++) {
            uint32_t kOff = (uint32_t)(kk * 32);
            uint32_t a[4][4];
            #pragma unroll
            for (int mi = 0; mi < 4; mi++)
                ldsm_x4(a[mi][0], a[mi][1], a[mi][2], a[mi][3],
                        aB + (uint32_t)(mi * 16 * PITCH) + kOff);
            uint32_t bf[4][2];
            #pragma unroll
            for (int p = 0; p < 2; p++) {
                uint32_t r0, r1, r2, r3;
                ldsm_x4(r0, r1, r2, r3, bB + (uint32_t)(p * 16 * PITCH) + kOff);
                bf[2 * p][0] = r0;     bf[2 * p][1] = r1;
                bf[2 * p + 1][0] = r2; bf[2 * p + 1][1] = r3;
            }
            #pragma unroll
            for (int mi = 0; mi < 4; mi++)
                #pragma unroll
                for (int nj = 0; nj < 4; nj++)
                    mma_16816(c[mi][nj], a[mi], bf[nj]);
        }

        if (++st >= 3) st -= 3;
    }

    // epilogue: evict-first streaming stores — keep A/B operands resident in L2
    int g = lane >> 2, tg = lane & 3;
    long rowBase = (long)(b * Mm + mb * 128 + wm * 64);
    int colBase = nb * 128 + wn * 32 + 2 * tg;
    #pragma unroll
    for (int mi = 0; mi < 4; mi++) {
        #pragma unroll
        for (int nj = 0; nj < 4; nj++) {
            float2* p0 = reinterpret_cast<float2*>(out + (rowBase + mi * 16 + g) * Nn + colBase + nj * 8);
            float2* p1 = reinterpret_cast<float2*>(out + (rowBase + mi * 16 + g + 8) * Nn + colBase + nj * 8);
            __stcs(p0, make_float2(c[mi][nj][0], c[mi][nj][1]));
            __stcs(p1, make_float2(c[mi][nj][2], c[mi][nj][3]));
        }
    }
}

// ================= block reduce helpers (512 threads = 16 warps) =================
__device__ __forceinline__ float block_sum(float v, float* red)
{
    int tid = threadIdx.x, lid = tid & 31, wid = tid >> 5;
    #pragma unroll
    for (int o = 16; o; o >>= 1) v += __shfl_xor_sync(0xffffffffu, v, o);
    if (lid == 0) red[wid] = v;
    __syncthreads();
    if (wid == 0) {
        float w = (lid < 16) ? red[lid] : 0.0f;
        #pragma unroll
        for (int o = 8; o; o >>= 1) w += __shfl_xor_sync(0xffffffffu, w, o);
        if (lid == 0) red[0] = w;
    }
    __syncthreads();
    float r = red[0];
    __syncthreads();
    return r;
}
__device__ __forceinline__ float block_max(float v, float* red)
{
    int tid = threadIdx.x, lid = tid & 31, wid = tid >> 5;
    #pragma unroll
    for (int o = 16; o; o >>= 1) v = fmaxf(v, __shfl_xor_sync(0xffffffffu, v, o));
    if (lid == 0) red[wid] = v;
    __syncthreads();
    if (wid == 0) {
        float w = (lid < 16) ? red[lid] : -3.0e38f;
        #pragma unroll
        for (int o = 8; o; o >>= 1) w = fmaxf(w, __shfl_xor_sync(0xffffffffu, w, o));
        if (lid == 0) red[0] = w;
    }
    __syncthreads();
    float r = red[0];
    __syncthreads();
    return r;
}

// ================= K3: softmax + sqrt-transform, t -> fp16, col partials =====
// 16 rows per CTA, streaming loads (__ldcs), next-row prefetch before both reduces.
__global__ void __launch_bounds__(512) softmax_kernel(const float* __restrict__ buf,
                                                      const float* __restrict__ mask)
{
    __shared__ float red[16];
    int mblk = blockIdx.x;          // 0..63
    int b = blockIdx.y;             // 0..15
    int tid = threadIdx.x;
    long row0 = (long)b * Mm + mblk * 16;

    float ca[8];
    #pragma unroll
    for (int j = 0; j < 8; j++) ca[j] = 0.0f;

    float4 x[2], mv[2];
    {
        const float4* xr = reinterpret_cast<const float4*>(buf + row0 * Nn);
        const float4* mr = reinterpret_cast<const float4*>(mask + row0 * Nn);
        x[0] = __ldcs(xr + tid); x[1] = __ldcs(xr + tid + 512);
        mv[0] = __ldcs(mr + tid); mv[1] = __ldcs(mr + tid + 512);
    }

    #pragma unroll 1
    for (int r = 0; r < 16; r++) {
        long row = row0 + r;

        float xi[8], mq[8];
        float lmx = -3.0e38f;
        #pragma unroll
        for (int j = 0; j < 2; j++) {
            const float* xp = reinterpret_cast<const float*>(&x[j]);
            const float* mp = reinterpret_cast<const float*>(&mv[j]);
            #pragma unroll
            for (int k = 0; k < 4; k++) {
                float m = mp[k];
                float v = (m < 1e-9f) ? -1e9f : xp[k];
                xi[j * 4 + k] = v;
                mq[j * 4 + k] = m + 1e-9f;
                lmx = fmaxf(lmx, v);
            }
        }

        if (r < 15) {
            const float4* xr = reinterpret_cast<const float4*>(buf + (row + 1) * Nn);
            const float4* mr = reinterpret_cast<const float4*>(mask + (row + 1) * Nn);
            x[0] = __ldcs(xr + tid); x[1] = __ldcs(xr + tid + 512);
            mv[0] = __ldcs(mr + tid); mv[1] = __ldcs(mr + tid + 512);
        }

        float rm = block_max(lmx, red);

        float s = 0.0f;
        #pragma unroll
        for (int j = 0; j < 8; j++) { xi[j] = __expf(xi[j] - rm); s += xi[j]; }
        s = block_sum(s, red);
        float inv = 1.0f / s;

        float2* tw = reinterpret_cast<float2*>(g_T + row * Nn);
        #pragma unroll
        for (int j = 0; j < 2; j++) {
            __half h4[4];
            #pragma unroll
            for (int k = 0; k < 4; k++) {
                float p = xi[j * 4 + k] * inv;
                float t = sqrtf(mq[j * 4 + k] * (p + 1e-9f)) - 1e-9f;
                h4[k] = __float2half_rn(t);
                ca[j * 4 + k] += __half2float(h4[k]);
            }
            __stcs(tw + tid + j * 512, *reinterpret_cast<float2*>(h4));
        }
    }

    float4* part = reinterpret_cast<float4*>(g_partial[mblk] + b * Nn);
    #pragma unroll
    for (int j = 0; j < 2; j++) {
        float4 o;
        o.x = ca[j * 4 + 0]; o.y = ca[j * 4 + 1];
        o.z = ca[j * 4 + 2]; o.w = ca[j * 4 + 3];
        part[tid + j * 512] = o;
    }
}

// ================= K3b: finalize column sums =================
__global__ void __launch_bounds__(256) colsum_fin_kernel()
{
    int i = blockIdx.x * 256 + threadIdx.x;
    float s = 0.0f;
    #pragma unroll
    for (int ms = 0; ms < Mm / 16; ms++) s += __ldcs(&g_partial[ms][i]);
    g_rcolsum[i] = 1.0f / fmaxf(s, 1e-12f);
}

// ================= K4: column norm + row norm (half t in, fp32 out) =================
__global__ void __launch_bounds__(512) norm_kernel(float* __restrict__ out)
{
    __shared__ float red[16];
    long row = blockIdx.x;
    int b = (int)(row >> 10);
    const uint2* tr = reinterpret_cast<const uint2*>(g_T + row * Nn);
    const float4* rc = reinterpret_cast<const float4*>(g_rcolsum + b * Nn);
    float4* ow = reinterpret_cast<float4*>(out + row * Nn);
    int tid = threadIdx.x;

    float u[2][4];
    float s = 0.0f;
    #pragma unroll
    for (int j = 0; j < 2; j++) {
        uint2 tv = __ldcs(tr + tid + j * 512);
        const __half* hp = reinterpret_cast<const __half*>(&tv);
        float4 r = rc[tid + j * 512];
        u[j][0] = __half2float(hp[0]) * r.x;
        u[j][1] = __half2float(hp[1]) * r.y;
        u[j][2] = __half2float(hp[2]) * r.z;
        u[j][3] = __half2float(hp[3]) * r.w;
        s += u[j][0] + u[j][1] + u[j][2] + u[j][3];
    }
    s = block_sum(s, red);
    float inv = 1.0f / fmaxf(s, 1e-12f);
    #pragma unroll
    for (int j = 0; j < 2; j++) {
        float4 o;
        o.x = u[j][0] * inv; o.y = u[j][1] * inv;
        o.z = u[j][2] * inv; o.w = u[j][3] * inv;
        __stcs(ow + tid + j * 512, o);
    }
}

// ================= launch =================
extern "C" void kernel_launch(void* const* d_in, const int* in_sizes, int n_in,
                              void* d_out, int out_size)
{
    const float* cent = (const float*)d_in[0];
    const float* feat = (const float*)d_in[1];
    const float* mask = (const float*)d_in[2];
    const float* Wq = (const float*)d_in[3];
    const float* Wk = (const float*)d_in[4];
    const float* gq = (const float*)d_in[5];
    const float* bq = (const float*)d_in[6];
    const float* mq = (const float*)d_in[7];
    const float* vq = (const float*)d_in[8];
    const float* gk = (const float*)d_in[9];
    const float* bk = (const float*)d_in[10];
    const float* mk = (const float*)d_in[11];
    const float* vk = (const float*)d_in[12];
    float* out = (float*)d_out;

    qk_kernel<<<(Bb * Mm + Bb * Nn) / 64, 128>>>(cent, feat, Wq, Wk,
                                                 gq, bq, mq, vq, gk, bk, mk, vk);

    cudaFuncSetAttribute(gemm_kernel, cudaFuncAttributeMaxDynamicSharedMemorySize, GEMM_SMEM);
    gemm_kernel<<<dim3(Nn / 128, Mm / 128, Bb), 256, GEMM_SMEM>>>(out);

    softmax_kernel<<<dim3(Mm / 16, Bb), 512>>>(out, mask);

    colsum_fin_kernel<<<(Bb * Nn) / 256, 256>>>();

    norm_kernel<<<Bb * Mm, 512>>>(out);
}